// round 14
// baseline (speedup 1.0000x reference)
#include <cuda_runtime.h>

// FastECT: per-(batch,bin,theta) histogram + cumsum over bins.
// N=200000 pts (D=3), T=128 thetas, R=128 bins, B=64 batches, batch sorted.
//
// R14 = R13 + lane-predicated histogram updates:
//  - ~32% of lane-updates clamp to bin 0/127 (nh~N(0,1)). Those lanes are
//    counted in registers (r0/r127, pure ALU) and the smem ATOMS is
//    PREDICATED OFF via inline-asm @p red.shared (no BSSY/BSYNC -- ptxas
//    won't emit this from C++ if, so it's hand-written PTX). If ATOMS cost
//    scales with active lanes (quickref: ~2cyc/lane spread), this cuts the
//    update wall ~32%.
//  - r0/r127 fold into the hist via 2 extra red.shared per thread/segment.
//  - Layout: u8, 4 bins/word/thread: word=(bin>>2)*128+t -> bank t%32 for
//    any bin (conflict-free). Vectorized flush (R13): LDS.128 + STS.128 +
//    red.global.add.v4.f32, ownership transposed, exact integer f32 adds.

#define TT 128
#define RR 128
#define NBLK 888     // 148 SMs * 6 resident, single balanced wave
#define TILE 256     // points staged per tile (SoA)

typedef unsigned int       u32;
typedef unsigned char      u8;
typedef unsigned long long u64;

__device__ __forceinline__ int lower_bound_i32(const int* __restrict__ a, int n, int key) {
    int lo = 0, hi = n;
    while (lo < hi) {
        int mid = (lo + hi) >> 1;
        if (a[mid] < key) lo = mid + 1; else hi = mid;
    }
    return lo;
}

// packed f32x2 helpers (sm_103a)
__device__ __forceinline__ u64 pack2(float lo, float hi) {
    u64 r; asm("mov.b64 %0, {%1, %2};" : "=l"(r) : "f"(lo), "f"(hi)); return r;
}
__device__ __forceinline__ void unpack2(u64 v, float& lo, float& hi) {
    asm("mov.b64 {%0, %1}, %2;" : "=f"(lo), "=f"(hi) : "l"(v));
}
__device__ __forceinline__ u64 mul2(u64 a, u64 b) {
    u64 r; asm("mul.rn.f32x2 %0, %1, %2;" : "=l"(r) : "l"(a), "l"(b)); return r;
}
__device__ __forceinline__ u64 fma2(u64 a, u64 b, u64 c) {
    u64 r; asm("fma.rn.f32x2 %0, %1, %2, %3;" : "=l"(r) : "l"(a), "l"(b), "l"(c)); return r;
}

// bin = clip(floor(f), 0, 127) for f = 64*nh + 64 (== (nh+1)*64 exactly)
__device__ __forceinline__ u32 bin_clamp(float f) {
    return min(__float2uint_rz(f), 127u);
}

// unconditional fire-and-forget smem add
__device__ __forceinline__ void reds_add(u32 smem_addr, u32 val) {
    asm volatile("red.shared.add.u32 [%0], %1;" :: "r"(smem_addr), "r"(val) : "memory");
}

// predicated: add only if 1 <= bn <= 126  ((bn-1) < 126 unsigned)
__device__ __forceinline__ void reds_add_interior(u32 smem_addr, u32 val, u32 bn) {
    asm volatile("{\n\t"
                 ".reg .pred p;\n\t"
                 "setp.lt.u32 p, %2, 126;\n\t"
                 "@p red.shared.add.u32 [%0], %1;\n\t"
                 "}" :: "r"(smem_addr), "r"(val), "r"(bn - 1u) : "memory");
}

// vector f32x4 global reduction (sm_90+), 16B-aligned address
__device__ __forceinline__ void redg_v4_f32(float* gaddr, float4 v) {
    asm volatile("red.global.add.v4.f32 [%0], {%1, %2, %3, %4};"
                 :: "l"(gaddr), "f"(v.x), "f"(v.y), "f"(v.z), "f"(v.w) : "memory");
}

__global__ void __launch_bounds__(256)
k_zero(float* __restrict__ out, int n4) {
    int i = blockIdx.x * blockDim.x + threadIdx.x;
    if (i < n4) ((float4*)out)[i] = make_float4(0.f, 0.f, 0.f, 0.f);
}

__global__ void __launch_bounds__(128, 6)
k_hist(const float* __restrict__ x, const float* __restrict__ v,
       const int* __restrict__ batch, int n, float* __restrict__ out) {
    __shared__ u8 H[RR * TT];                    // u8, 4 bins/word/thread
    __shared__ float SX[TILE], SY[TILE], SZ[TILE];
    __shared__ float4 XF[4][32];                 // flush prefix exchange
    __shared__ int seg_end_sh;

    const int t = threadIdx.x;
    const int g = blockIdx.x;
    const u32 hbase = (u32)__cvta_generic_to_shared(H) + ((u32)t << 2);

    const int lo = (int)(((long long)g)     * n / NBLK);
    const int hi = (int)(((long long)g + 1) * n / NBLK);

    const float v0 = v[t];
    const float v1 = v[TT + t];
    const float v2 = v[2 * TT + t];
    const u64 v0p = pack2(v0, v0), v1p = pack2(v1, v1), v2p = pack2(v2, v2);
    const u64 c64p = pack2(64.0f, 64.0f);

    // zero 16KB histogram (conflict-free uint4 stores)
    {
        uint4* a = (uint4*)H;
        for (int i = t; i < (RR * TT) / 16; i += 128)
            a[i] = make_uint4(0u, 0u, 0u, 0u);
    }

    int pos = lo;
    while (pos < hi) {
        if (t == 0) {
            int b = batch[pos];
            seg_end_sh = min(hi, lower_bound_i32(batch, n, b + 1));
        }
        __syncthreads();
        const int seg_end = seg_end_sh;
        const int b = batch[pos];                // uniform broadcast

        u32 r0 = 0, r127 = 0;                    // clamp-lane register counts

        for (int base = pos; base < seg_end; base += TILE) {
            const int m = min(TILE, seg_end - base);
            for (int p = t; p < m; p += 128) {
                const float* src = x + (size_t)(base + p) * 3;
                SX[p] = src[0]; SY[p] = src[1]; SZ[p] = src[2];
            }
            __syncthreads();

            int k = 0;
            for (; k + 4 <= m; k += 4) {
                ulonglong2 X = *(const ulonglong2*)(SX + k);
                ulonglong2 Y = *(const ulonglong2*)(SY + k);
                ulonglong2 Z = *(const ulonglong2*)(SZ + k);
                u64 nhA = fma2(Z.x, v2p, fma2(Y.x, v1p, mul2(X.x, v0p)));
                u64 nhB = fma2(Z.y, v2p, fma2(Y.y, v1p, mul2(X.y, v0p)));
                u64 fA  = fma2(nhA, c64p, c64p);
                u64 fB  = fma2(nhB, c64p, c64p);
                float f0, f1, f2, f3;
                unpack2(fA, f0, f1);
                unpack2(fB, f2, f3);
                u32 b0 = bin_clamp(f0), b1 = bin_clamp(f1);
                u32 b2 = bin_clamp(f2), b3 = bin_clamp(f3);
                // clamp lanes -> registers (ALU), interior -> predicated ATOMS
                r0   += (b0 == 0u)   + (b1 == 0u)   + (b2 == 0u)   + (b3 == 0u);
                r127 += (b0 == 127u) + (b1 == 127u) + (b2 == 127u) + (b3 == 127u);
                reds_add_interior(hbase + ((b0 >> 2) << 9), 1u << ((b0 & 3u) << 3), b0);
                reds_add_interior(hbase + ((b1 >> 2) << 9), 1u << ((b1 & 3u) << 3), b1);
                reds_add_interior(hbase + ((b2 >> 2) << 9), 1u << ((b2 & 3u) << 3), b2);
                reds_add_interior(hbase + ((b3 >> 2) << 9), 1u << ((b3 & 3u) << 3), b3);
            }
            for (; k < m; ++k) {
                float nh = fmaf(SZ[k], v2, fmaf(SY[k], v1, __fmul_rn(SX[k], v0)));
                u32 bn = bin_clamp(fmaf(nh, 64.0f, 64.0f));
                r0   += (bn == 0u);
                r127 += (bn == 127u);
                reds_add_interior(hbase + ((bn >> 2) << 9), 1u << ((bn & 3u) << 3), bn);
            }
            __syncthreads();                     // tile drain
        }

        // fold register clamp counts into the hist (bin0 -> word0 byte0,
        // bin127 -> word31 byte3), then drain before flush.
        reds_add(hbase, r0);
        reds_add(hbase + (31u << 9), r127 << 24);
        __syncthreads();

        // ---- vectorized flush (R13) ----
        // warp w owns bins [32w, 32w+32); lane l owns thetas 4l..4l+3.
        {
            const int w = t >> 5, l = t & 31;
            u32* hw = (u32*)H;
            uint4 W[8];
            u32 s0 = 0, s1 = 0, s2 = 0, s3 = 0;
#pragma unroll
            for (int i = 0; i < 8; ++i) {
                uint4* p = (uint4*)(hw + ((8 * w + i) * 128 + 4 * l));
                W[i] = *p;                       // 4 thetas x 4 bins
                *p = make_uint4(0u, 0u, 0u, 0u); // rezero (own read slot)
                s0 = __dp4a(W[i].x, 0x01010101u, s0);
                s1 = __dp4a(W[i].y, 0x01010101u, s1);
                s2 = __dp4a(W[i].z, 0x01010101u, s2);
                s3 = __dp4a(W[i].w, 0x01010101u, s3);
            }
            XF[w][l] = make_float4((float)s0, (float)s1, (float)s2, (float)s3);
            __syncthreads();
            float4 acc = make_float4(0.f, 0.f, 0.f, 0.f);
            for (int w2 = 0; w2 < w; ++w2) {     // warp-uniform trip count
                float4 p = XF[w2][l];
                acc.x += p.x; acc.y += p.y; acc.z += p.z; acc.w += p.w;
            }
            float* dst = out + ((size_t)b * RR + 32 * w) * TT + 4 * l;
#pragma unroll
            for (int i = 0; i < 8; ++i) {
#pragma unroll
                for (int s = 0; s < 4; ++s) {
                    acc.x += (float)((W[i].x >> (8 * s)) & 255u);
                    acc.y += (float)((W[i].y >> (8 * s)) & 255u);
                    acc.z += (float)((W[i].z >> (8 * s)) & 255u);
                    acc.w += (float)((W[i].w >> (8 * s)) & 255u);
                    redg_v4_f32(dst + (size_t)(i * 4 + s) * TT, acc);
                }
            }
        }
        pos = seg_end;
        __syncthreads();                         // XF/H reuse + zero ordering
    }
}

extern "C" void kernel_launch(void* const* d_in, const int* in_sizes, int n_in,
                              void* d_out, int out_size) {
    const float* x     = (const float*)d_in[0];   // [200000, 3]
    const float* v     = (const float*)d_in[1];   // [3, 128]
    const int*   batch = (const int*)d_in[2];     // [200000], sorted
    const int n = in_sizes[2];

    float* out = (float*)d_out;                   // [64, 128, 128]
    const int n4 = out_size / 4;

    k_zero<<<(n4 + 255) / 256, 256>>>(out, n4);
    k_hist<<<NBLK, 128>>>(x, v, batch, n, out);
}

// round 15
// speedup vs baseline: 1.3171x; 1.3171x over previous
#include <cuda_runtime.h>

// FastECT: per-(batch,bin,theta) histogram + cumsum over bins.
// N=200000 pts (D=3), T=128 thetas, R=128 bins, B=64 batches, batch sorted.
//
// R15 = R11 hot loop (fire-and-forget red.shared updates) with halved
// per-block overhead. red.shared has NO return dependency -> needs no
// latency hiding -> occupancy demand is low; so drop to 592 blocks (4/SM)
// and amortize zero+flush over 2x the points (R5/R6 slope: ~5us per 592
// blocks of overhead). Counter safety at 338 pts/block: u16 half-words,
// 2 bins per 32-bit word per thread (word = (bin>>1)*128 + t -> bank t%32
// for any bin, conflict-free; counts <= 65535, always exact).
// TILE=512 halves tile barriers. cumsum linear => flush cumsum(partial)
// into d_out via f32 atomicAdd (exact integer adds, deterministic).

#define TT 128
#define RR 128
#define NBLK 592     // 148 SMs * 4 resident, single balanced wave
#define TILE 512     // points staged per tile (SoA)

typedef unsigned int       u32;
typedef unsigned char      u8;
typedef unsigned long long u64;

__device__ __forceinline__ int lower_bound_i32(const int* __restrict__ a, int n, int key) {
    int lo = 0, hi = n;
    while (lo < hi) {
        int mid = (lo + hi) >> 1;
        if (a[mid] < key) lo = mid + 1; else hi = mid;
    }
    return lo;
}

// packed f32x2 helpers (sm_103a): same per-lane rounding as scalar chain
__device__ __forceinline__ u64 pack2(float lo, float hi) {
    u64 r; asm("mov.b64 %0, {%1, %2};" : "=l"(r) : "f"(lo), "f"(hi)); return r;
}
__device__ __forceinline__ void unpack2(u64 v, float& lo, float& hi) {
    asm("mov.b64 {%0, %1}, %2;" : "=f"(lo), "=f"(hi) : "l"(v));
}
__device__ __forceinline__ u64 mul2(u64 a, u64 b) {
    u64 r; asm("mul.rn.f32x2 %0, %1, %2;" : "=l"(r) : "l"(a), "l"(b)); return r;
}
__device__ __forceinline__ u64 fma2(u64 a, u64 b, u64 c) {
    u64 r; asm("fma.rn.f32x2 %0, %1, %2, %3;" : "=l"(r) : "l"(a), "l"(b), "l"(c)); return r;
}

// bin = clip(floor(f), 0, 127) for f = 64*nh + 64 (== (nh+1)*64 exactly)
__device__ __forceinline__ u32 bin_clamp(float f) {
    return min(__float2uint_rz(f), 127u);
}

// fire-and-forget smem add (ATOMS.ADD no-return)
__device__ __forceinline__ void reds_add(u32 smem_addr, u32 val) {
    asm volatile("red.shared.add.u32 [%0], %1;" :: "r"(smem_addr), "r"(val) : "memory");
}

__global__ void __launch_bounds__(256)
k_zero(float* __restrict__ out, int n4) {
    int i = blockIdx.x * blockDim.x + threadIdx.x;
    if (i < n4) ((float4*)out)[i] = make_float4(0.f, 0.f, 0.f, 0.f);
}

__global__ void __launch_bounds__(128, 4)
k_hist(const float* __restrict__ x, const float* __restrict__ v,
       const int* __restrict__ batch, int n, float* __restrict__ out) {
    __shared__ u32 H[(RR / 2) * TT];             // u16x2: 2 bins/word/thread
    __shared__ float SX[TILE], SY[TILE], SZ[TILE];
    __shared__ int seg_end_sh;

    const int t = threadIdx.x;
    const int g = blockIdx.x;
    const u32 hbase = (u32)__cvta_generic_to_shared(H) + ((u32)t << 2);

    const int lo = (int)(((long long)g)     * n / NBLK);
    const int hi = (int)(((long long)g + 1) * n / NBLK);

    const float v0 = v[t];
    const float v1 = v[TT + t];
    const float v2 = v[2 * TT + t];
    const u64 v0p = pack2(v0, v0), v1p = pack2(v1, v1), v2p = pack2(v2, v2);
    const u64 c64p = pack2(64.0f, 64.0f);

    // zero 32KB histogram (conflict-free uint4 stores)
    {
        uint4* a = (uint4*)H;
        for (int i = t; i < (RR / 2) * TT / 4; i += 128)
            a[i] = make_uint4(0u, 0u, 0u, 0u);
    }

    int pos = lo;
    while (pos < hi) {
        if (t == 0) {
            int b = batch[pos];
            seg_end_sh = min(hi, lower_bound_i32(batch, n, b + 1));
        }
        __syncthreads();
        const int seg_end = seg_end_sh;
        const int b = batch[pos];                // uniform broadcast

        for (int base = pos; base < seg_end; base += TILE) {
            const int m = min(TILE, seg_end - base);
            for (int p = t; p < m; p += 128) {
                const float* src = x + (size_t)(base + p) * 3;
                SX[p] = src[0]; SY[p] = src[1]; SZ[p] = src[2];
            }
            __syncthreads();

            int k = 0;
            for (; k + 4 <= m; k += 4) {
                // warp-uniform LDS.128 -> packed f32x2 component pairs
                ulonglong2 X = *(const ulonglong2*)(SX + k);
                ulonglong2 Y = *(const ulonglong2*)(SY + k);
                ulonglong2 Z = *(const ulonglong2*)(SZ + k);
                u64 nhA = fma2(Z.x, v2p, fma2(Y.x, v1p, mul2(X.x, v0p)));
                u64 nhB = fma2(Z.y, v2p, fma2(Y.y, v1p, mul2(X.y, v0p)));
                u64 fA  = fma2(nhA, c64p, c64p); // == (nh+1)*64 exactly
                u64 fB  = fma2(nhB, c64p, c64p);
                float f0, f1, f2, f3;
                unpack2(fA, f0, f1);
                unpack2(fB, f2, f3);
                u32 b0 = bin_clamp(f0), b1 = bin_clamp(f1);
                u32 b2 = bin_clamp(f2), b3 = bin_clamp(f3);
                // one no-return smem reduction per update (bank t%32):
                // word = (bin>>1)*128 + t, halfword = bin&1
                reds_add(hbase + ((b0 >> 1) << 9), 1u << ((b0 & 1u) << 4));
                reds_add(hbase + ((b1 >> 1) << 9), 1u << ((b1 & 1u) << 4));
                reds_add(hbase + ((b2 >> 1) << 9), 1u << ((b2 & 1u) << 4));
                reds_add(hbase + ((b3 >> 1) << 9), 1u << ((b3 & 1u) << 4));
            }
            for (; k < m; ++k) {
                float nh = fmaf(SZ[k], v2, fmaf(SY[k], v1, __fmul_rn(SX[k], v0)));
                u32 bn = bin_clamp(fmaf(nh, 64.0f, 64.0f));
                reds_add(hbase + ((bn >> 1) << 9), 1u << ((bn & 1u) << 4));
            }
            __syncthreads();                     // drains pending reductions
        }

        // flush: cumsum(partial) += out[b][bin][t]; fully unrolled.
        // LDS word (bin>>1)*128 + t (bank t%32), REDG coalesced across t.
        {
            int acc = 0;
            float* dst = out + ((size_t)b * RR) * TT + t;
#pragma unroll
            for (int bin2 = 0; bin2 < RR / 2; ++bin2) {
                u32 w = H[bin2 * 128 + t];
                H[bin2 * 128 + t] = 0u;          // rezero for next segment
                acc += (int)(w & 0xFFFFu);
                atomicAdd(dst + (bin2 * 2 + 0) * TT, (float)acc);
                acc += (int)(w >> 16);
                atomicAdd(dst + (bin2 * 2 + 1) * TT, (float)acc);
            }
        }
        pos = seg_end;
        __syncthreads();                         // protect stage/hist reuse
    }
}

extern "C" void kernel_launch(void* const* d_in, const int* in_sizes, int n_in,
                              void* d_out, int out_size) {
    const float* x     = (const float*)d_in[0];   // [200000, 3]
    const float* v     = (const float*)d_in[1];   // [3, 128]
    const int*   batch = (const int*)d_in[2];     // [200000], sorted
    const int n = in_sizes[2];

    float* out = (float*)d_out;                   // [64, 128, 128]
    const int n4 = out_size / 4;

    k_zero<<<(n4 + 255) / 256, 256>>>(out, n4);
    k_hist<<<NBLK, 128>>>(x, v, batch, n, out);
}